// round 3
// baseline (speedup 1.0000x reference)
#include <cuda_runtime.h>
#include <cuda_bf16.h>

// GraphAddPooling: out[g] = sum_{i: batch[i]==g} x[i]
// x: [200000, 256] fp32, batch: sorted (int32 or int64, detected), out: [512, 256] fp32.
//
// One block per (segment, column-quarter). batch sorted => segment g = rows
// [lower_bound(g), lower_bound(g+1)). 2048 blocks of 128 threads: 16 float4
// lanes (64 columns) x 8 row-streams, depth-2 prefetch, smem combine, plain
// STG (disjoint columns per block -> no atomics, no zero pass, 1 launch).
// 2048 blocks = 16 CTAs/SM, all co-resident: per-SM work imbalance ~7%
// (vs 33% with the previous 512-block grid).

#define NCOLS   256
#define VCOLS   64      // float4 per full row
#define CSPLIT  4       // column quarters per segment
#define LANES   16      // float4 lanes per quarter (64 cols = 256B)
#define STREAMS 8
#define TPB     128

// Warp-cooperative lower_bound over sorted segment ids.
// shift==1 when batch is int64 (probe low int32 words), 0 when int32.
__device__ __forceinline__ int warp_lower_bound(const int* __restrict__ b,
                                                int shift, int n,
                                                int target, int lane) {
    int lo = 0, rem = n;
    while (rem > 0) {
        int chunk = (rem + 32) / 33;                       // 33-way partition
        long p = (long)lo + (long)chunk * (lane + 1) - 1;  // end of lane's chunk
        bool lt = false;
        if (p < (long)lo + rem) lt = (b[p << shift] < target);
        unsigned m = __ballot_sync(0xffffffffu, lt);
        int k = __popc(m);
        lo += k * chunk;
        int r2 = rem - k * chunk;
        rem = (r2 <= 0) ? 0 : ((r2 >= chunk) ? (chunk - 1) : r2);
    }
    return lo;   // first index with b[i] >= target (== n if none)
}

__global__ __launch_bounds__(TPB, 16) void gap_seg_kernel(
    const float4* __restrict__ x,
    const int* __restrict__ b32,     // batch viewed as int32 words
    float4* __restrict__ out,
    int nrows)
{
    __shared__ int    s_bounds[2];
    __shared__ float4 s_part[STREAMS][LANES];

    const int g     = blockIdx.x >> 2;       // segment
    const int cq    = blockIdx.x & 3;        // column quarter
    const int tid   = threadIdx.x;
    const int lane  = tid & (LANES - 1);     // float4 lane within quarter
    const int ys    = tid >> 4;              // row stream 0..7
    const int wlane = tid & 31;
    const int wid   = tid >> 5;

    // int64 vs int32 batch: sorted ids < 512, so if stored as int64 the
    // int32 word at index nrows-1 is a high word (== 0).
    const int shift = (b32[nrows - 1] == 0) ? 1 : 0;

    if (wid < 2) {
        int r = warp_lower_bound(b32, shift, nrows, g + wid, wlane);
        if (wlane == 0) s_bounds[wid] = r;
    }
    __syncthreads();
    const int lo = s_bounds[0];
    const int hi = s_bounds[1];

    const float4* xq = x + (size_t)cq * LANES + lane;   // column offset

    // Stream rows lo+ys, lo+ys+8, ... with depth-2 prefetch.
    float4 acc = make_float4(0.f, 0.f, 0.f, 0.f);
    int r = lo + ys;
    float4 v = make_float4(0.f, 0.f, 0.f, 0.f);
    if (r < hi) v = __ldcs(xq + (size_t)r * VCOLS);

    while (r < hi) {
        int rn = r + STREAMS;
        float4 vn = make_float4(0.f, 0.f, 0.f, 0.f);
        if (rn < hi) vn = __ldcs(xq + (size_t)rn * VCOLS);
        acc.x += v.x; acc.y += v.y; acc.z += v.z; acc.w += v.w;
        r = rn; v = vn;
    }

    s_part[ys][lane] = acc;
    __syncthreads();

    if (tid < LANES) {
        float4 a = s_part[0][tid];
        #pragma unroll
        for (int s = 1; s < STREAMS; s++) {
            float4 b = s_part[s][tid];
            a.x += b.x; a.y += b.y; a.z += b.z; a.w += b.w;
        }
        // Disjoint (segment, quarter) output -> unconditional plain store.
        out[(size_t)g * VCOLS + cq * LANES + tid] = a;
    }
}

extern "C" void kernel_launch(void* const* d_in, const int* in_sizes, int n_in,
                              void* d_out, int out_size) {
    const float4* x  = (const float4*)d_in[0];
    const int* batch = (const int*)d_in[1];
    float4* out      = (float4*)d_out;

    const int nrows = in_sizes[1];        // 200000
    const int nseg  = out_size / NCOLS;   // 512

    gap_seg_kernel<<<nseg * CSPLIT, TPB>>>(x, batch, out, nrows);
}